// round 1
// baseline (speedup 1.0000x reference)
#include <cuda_runtime.h>
#include <cuda_bf16.h>
#include <math.h>

// Problem constants
#define B_   4
#define N_   2048
#define DIM_ 1024
#define H_   16
#define D_   64
#define M_   (B_ * N_)          // 8192 rows
#define QKVN (3 * DIM_)         // 3072
#define SCALE_ 0.03125f         // 1024^-0.5

// ---------------- scratch (device globals; no allocation APIs) ----------------
__device__ float g_q[B_ * H_ * N_ * D_];     // [b,h,n,d]
__device__ float g_k[B_ * H_ * N_ * D_];
__device__ float g_v[B_ * H_ * N_ * D_];
__device__ float g_attn[M_ * DIM_];          // [b,n,h*d]

// ---------------- GEMM1: qkv = x @ w_qkv, scatter to q/k/v heads --------------
#define GBM 128
#define GBN 128
#define GBK 8
#define GTM 8
#define GTN 8

__global__ __launch_bounds__(256) void gemm_qkv_kernel(const float* __restrict__ X,
                                                       const float* __restrict__ W) {
    const int K = DIM_, NN = QKVN;
    __shared__ float As[GBK][GBM];
    __shared__ float Bs[GBK][GBN];
    const int cRow = blockIdx.y, cCol = blockIdx.x;
    const int tid = threadIdx.x;
    const int tr = tid >> 4, tc = tid & 15;
    const float* A  = X + (size_t)cRow * GBM * K;
    const float* Bg = W + (size_t)cCol * GBN;
    const int aRow = tid >> 1, aCol = (tid & 1) << 2;
    const int bRow = tid >> 5, bCol = (tid & 31) << 2;

    float acc[GTM][GTN];
    #pragma unroll
    for (int i = 0; i < GTM; i++)
        #pragma unroll
        for (int j = 0; j < GTN; j++) acc[i][j] = 0.f;
    float regM[GTM], regN[GTN];

    for (int k0 = 0; k0 < K; k0 += GBK) {
        float4 av = *reinterpret_cast<const float4*>(&A[(size_t)aRow * K + k0 + aCol]);
        As[aCol + 0][aRow] = av.x;
        As[aCol + 1][aRow] = av.y;
        As[aCol + 2][aRow] = av.z;
        As[aCol + 3][aRow] = av.w;
        *reinterpret_cast<float4*>(&Bs[bRow][bCol]) =
            *reinterpret_cast<const float4*>(&Bg[(size_t)(k0 + bRow) * NN + bCol]);
        __syncthreads();
        #pragma unroll
        for (int kk = 0; kk < GBK; kk++) {
            #pragma unroll
            for (int i = 0; i < GTM; i++) regM[i] = As[kk][tr * GTM + i];
            #pragma unroll
            for (int j = 0; j < GTN; j++) regN[j] = Bs[kk][tc * GTN + j];
            #pragma unroll
            for (int i = 0; i < GTM; i++)
                #pragma unroll
                for (int j = 0; j < GTN; j++)
                    acc[i][j] += regM[i] * regN[j];
        }
        __syncthreads();
    }

    // scatter epilogue: col in [0,3072) -> which (q/k/v), head, d
    const int colBase = cCol * GBN;
    const int which = colBase / DIM_;             // uniform per CTA (128 | 1024)
    float* dst = (which == 0) ? g_q : (which == 1) ? g_k : g_v;
    const int colLoc = colBase - which * DIM_;
    #pragma unroll
    for (int i = 0; i < GTM; i++) {
        const int m = cRow * GBM + tr * GTM + i;
        const int b = m >> 11, n = m & (N_ - 1);
        #pragma unroll
        for (int j = 0; j < GTN; j++) {
            const int c = colLoc + tc * GTN + j;
            const int h = c >> 6, d = c & 63;
            dst[((((size_t)b * H_ + h) * N_) + n) * D_ + d] = acc[i][j];
        }
    }
}

// ---------------- Flash attention: per (q-block of 64, b*h) -------------------
#define FS 68   // smem row stride (floats), 16B-aligned rows, conflict-breaking

extern __shared__ float fsm[];

__global__ __launch_bounds__(256) void flash_kernel() {
    float* Qs = fsm;
    float* Ks = fsm + 64 * FS;
    float* Vs = fsm + 2 * 64 * FS;
    float* Ps = fsm + 3 * 64 * FS;

    const int bh = blockIdx.y;   // 0..63
    const int qb = blockIdx.x;   // 0..31
    const float* Qp = g_q + ((size_t)bh * N_ + qb * 64) * D_;
    const float* Kp = g_k + (size_t)bh * N_ * D_;
    const float* Vp = g_v + (size_t)bh * N_ * D_;

    const int tid = threadIdx.x;
    const int tr = tid >> 4, tc = tid & 15;

    // load Q tile [64][64]
    #pragma unroll
    for (int o = 0; o < 4; o++) {
        int lin = o * 256 + tid;
        int row = lin >> 4, c4 = (lin & 15) << 2;
        *reinterpret_cast<float4*>(&Qs[row * FS + c4]) =
            *reinterpret_cast<const float4*>(&Qp[row * 64 + c4]);
    }

    float m_i[4], l_i[4];
    float4 Ov[4];
    #pragma unroll
    for (int i = 0; i < 4; i++) {
        m_i[i] = -1e30f;
        l_i[i] = 0.f;
        Ov[i] = make_float4(0.f, 0.f, 0.f, 0.f);
    }

    for (int kt = 0; kt < N_ / 64; kt++) {
        __syncthreads();   // prior-iter smem reads complete (also covers Q load)
        #pragma unroll
        for (int o = 0; o < 4; o++) {
            int lin = o * 256 + tid;
            int row = lin >> 4, c4 = (lin & 15) << 2;
            *reinterpret_cast<float4*>(&Ks[row * FS + c4]) =
                *reinterpret_cast<const float4*>(&Kp[(kt * 64 + row) * 64 + c4]);
            *reinterpret_cast<float4*>(&Vs[row * FS + c4]) =
                *reinterpret_cast<const float4*>(&Vp[(kt * 64 + row) * 64 + c4]);
        }
        __syncthreads();

        // S[i][j] = sum_d Q[tr*4+i][d] * K[tc*4+j][d]
        float s[4][4];
        #pragma unroll
        for (int i = 0; i < 4; i++)
            #pragma unroll
            for (int j = 0; j < 4; j++) s[i][j] = 0.f;

        #pragma unroll
        for (int kk = 0; kk < 64; kk += 4) {
            float4 qa[4], kb[4];
            #pragma unroll
            for (int i = 0; i < 4; i++)
                qa[i] = *reinterpret_cast<const float4*>(&Qs[(tr * 4 + i) * FS + kk]);
            #pragma unroll
            for (int j = 0; j < 4; j++)
                kb[j] = *reinterpret_cast<const float4*>(&Ks[(tc * 4 + j) * FS + kk]);
            #pragma unroll
            for (int i = 0; i < 4; i++)
                #pragma unroll
                for (int j = 0; j < 4; j++)
                    s[i][j] += qa[i].x * kb[j].x + qa[i].y * kb[j].y +
                               qa[i].z * kb[j].z + qa[i].w * kb[j].w;
        }

        // online softmax update
        #pragma unroll
        for (int i = 0; i < 4; i++) {
            #pragma unroll
            for (int j = 0; j < 4; j++) s[i][j] *= SCALE_;
            float mx = fmaxf(fmaxf(s[i][0], s[i][1]), fmaxf(s[i][2], s[i][3]));
            #pragma unroll
            for (int off = 8; off >= 1; off >>= 1)
                mx = fmaxf(mx, __shfl_xor_sync(0xffffffffu, mx, off));
            float mn = fmaxf(m_i[i], mx);
            float alpha = __expf(m_i[i] - mn);
            float rs = 0.f;
            #pragma unroll
            for (int j = 0; j < 4; j++) {
                s[i][j] = __expf(s[i][j] - mn);
                rs += s[i][j];
            }
            #pragma unroll
            for (int off = 8; off >= 1; off >>= 1)
                rs += __shfl_xor_sync(0xffffffffu, rs, off);
            l_i[i] = l_i[i] * alpha + rs;
            m_i[i] = mn;
            Ov[i].x *= alpha; Ov[i].y *= alpha; Ov[i].z *= alpha; Ov[i].w *= alpha;
            *reinterpret_cast<float4*>(&Ps[(tr * 4 + i) * FS + tc * 4]) =
                make_float4(s[i][0], s[i][1], s[i][2], s[i][3]);
        }
        __syncthreads();

        // O[i][tc*4..+4] += sum_j P[i][j] * V[j][tc*4..+4]
        #pragma unroll
        for (int j = 0; j < 64; j += 4) {
            float4 pa[4], vb[4];
            #pragma unroll
            for (int i = 0; i < 4; i++)
                pa[i] = *reinterpret_cast<const float4*>(&Ps[(tr * 4 + i) * FS + j]);
            #pragma unroll
            for (int jj = 0; jj < 4; jj++)
                vb[jj] = *reinterpret_cast<const float4*>(&Vs[(j + jj) * FS + tc * 4]);
            #pragma unroll
            for (int i = 0; i < 4; i++) {
                Ov[i].x += pa[i].x * vb[0].x + pa[i].y * vb[1].x + pa[i].z * vb[2].x + pa[i].w * vb[3].x;
                Ov[i].y += pa[i].x * vb[0].y + pa[i].y * vb[1].y + pa[i].z * vb[2].y + pa[i].w * vb[3].y;
                Ov[i].z += pa[i].x * vb[0].z + pa[i].y * vb[1].z + pa[i].z * vb[2].z + pa[i].w * vb[3].z;
                Ov[i].w += pa[i].x * vb[0].w + pa[i].y * vb[1].w + pa[i].z * vb[2].w + pa[i].w * vb[3].w;
            }
        }
    }

    // normalize + write to [b, n, h*64 + d] layout
    const int b = bh >> 4, h = bh & 15;
    #pragma unroll
    for (int i = 0; i < 4; i++) {
        float inv = 1.f / l_i[i];
        int n = qb * 64 + tr * 4 + i;
        float4 o = make_float4(Ov[i].x * inv, Ov[i].y * inv, Ov[i].z * inv, Ov[i].w * inv);
        *reinterpret_cast<float4*>(
            &g_attn[((size_t)b * N_ + n) * DIM_ + h * 64 + tc * 4]) = o;
    }
}

// ---------------- GEMM2: out = g_attn @ w_out + b_out ------------------------
__global__ __launch_bounds__(256) void gemm_out_kernel(const float* __restrict__ Wout,
                                                       const float* __restrict__ bias,
                                                       float* __restrict__ out) {
    const int K = DIM_, NN = DIM_;
    __shared__ float As[GBK][GBM];
    __shared__ float Bs[GBK][GBN];
    const int cRow = blockIdx.y, cCol = blockIdx.x;
    const int tid = threadIdx.x;
    const int tr = tid >> 4, tc = tid & 15;
    const float* A  = g_attn + (size_t)cRow * GBM * K;
    const float* Bg = Wout + (size_t)cCol * GBN;
    const int aRow = tid >> 1, aCol = (tid & 1) << 2;
    const int bRow = tid >> 5, bCol = (tid & 31) << 2;

    float acc[GTM][GTN];
    #pragma unroll
    for (int i = 0; i < GTM; i++)
        #pragma unroll
        for (int j = 0; j < GTN; j++) acc[i][j] = 0.f;
    float regM[GTM], regN[GTN];

    for (int k0 = 0; k0 < K; k0 += GBK) {
        float4 av = *reinterpret_cast<const float4*>(&A[(size_t)aRow * K + k0 + aCol]);
        As[aCol + 0][aRow] = av.x;
        As[aCol + 1][aRow] = av.y;
        As[aCol + 2][aRow] = av.z;
        As[aCol + 3][aRow] = av.w;
        *reinterpret_cast<float4*>(&Bs[bRow][bCol]) =
            *reinterpret_cast<const float4*>(&Bg[(size_t)(k0 + bRow) * NN + bCol]);
        __syncthreads();
        #pragma unroll
        for (int kk = 0; kk < GBK; kk++) {
            #pragma unroll
            for (int i = 0; i < GTM; i++) regM[i] = As[kk][tr * GTM + i];
            #pragma unroll
            for (int j = 0; j < GTN; j++) regN[j] = Bs[kk][tc * GTN + j];
            #pragma unroll
            for (int i = 0; i < GTM; i++)
                #pragma unroll
                for (int j = 0; j < GTN; j++)
                    acc[i][j] += regM[i] * regN[j];
        }
        __syncthreads();
    }

    #pragma unroll
    for (int i = 0; i < GTM; i++) {
        const int m = cRow * GBM + tr * GTM + i;
        #pragma unroll
        for (int j = 0; j < GTN; j += 4) {
            const int col = cCol * GBN + tc * GTN + j;
            float4 bv = *reinterpret_cast<const float4*>(&bias[col]);
            float4 o = make_float4(acc[i][j] + bv.x, acc[i][j + 1] + bv.y,
                                   acc[i][j + 2] + bv.z, acc[i][j + 3] + bv.w);
            *reinterpret_cast<float4*>(&out[(size_t)m * NN + col]) = o;
        }
    }
}

// ---------------- launch ------------------------------------------------------
extern "C" void kernel_launch(void* const* d_in, const int* in_sizes, int n_in,
                              void* d_out, int out_size) {
    const float* x     = (const float*)d_in[0];
    const float* w_qkv = (const float*)d_in[1];
    const float* w_out = (const float*)d_in[2];
    const float* b_out = (const float*)d_in[3];
    float* out = (float*)d_out;

    dim3 blk(256);

    dim3 g1(QKVN / GBN, M_ / GBM);   // (24, 64)
    gemm_qkv_kernel<<<g1, blk>>>(x, w_qkv);

    const int fl_smem = 4 * 64 * FS * sizeof(float);  // 69632 B
    cudaFuncSetAttribute(flash_kernel, cudaFuncAttributeMaxDynamicSharedMemorySize, fl_smem);
    dim3 g2(N_ / 64, B_ * H_);       // (32, 64)
    flash_kernel<<<g2, blk, fl_smem>>>();

    dim3 g3(DIM_ / GBN, M_ / GBM);   // (8, 64)
    gemm_out_kernel<<<g3, blk>>>(w_out, b_out, out);
}